// round 2
// baseline (speedup 1.0000x reference)
#include <cuda_runtime.h>
#include <math.h>

// Problem dims
#define W 160
#define H 160
#define D 160
#define NB 2
#define PLANE (H * W)              // 25600
#define VOL (D * H * W)            // 4096000
#define NE (NB * VOL)              // 8192000
#define INV_SZ (1.0f / 125.0f)

// Sliding-pass decomposition: 160 = 5 chunks of 32
#define NCHUNK 5
#define CHUNK 32
#define NCOL (NB * 160 * 160)      // 51200 columns per axis pass
#define SLIDE_THREADS (NCOL * NCHUNK)  // 256000

// Scratch (allocation-free rule: __device__ globals)
__device__ float g_s1f[NE];
__device__ float g_s1m[NE];
__device__ float g_s2f[NE];
__device__ float g_s2m[NE];
__device__ float g_t0[NE];
__device__ float g_t1[NE];
__device__ float g_t2[NE];
__device__ float g_t3[NE];
__device__ double g_acc;

__device__ __forceinline__ float frsqrt_approx(float x) {
    float y;
    asm("rsqrt.approx.f32 %0, %1;" : "=f"(y) : "f"(x));
    return y;
}

// ---------------------------------------------------------------------------
// K0: zero accumulator (graph replays must be deterministic)
__global__ void k_zero_acc() { g_acc = 0.0; }

// ---------------------------------------------------------------------------
// K1: x-axis 5-tap clamped sum on two fields (stage 1 front)
__global__ void k_boxx_pair(const float* __restrict__ a, const float* __restrict__ b,
                            float* __restrict__ oa, float* __restrict__ ob) {
    int idx = blockIdx.x * blockDim.x + threadIdx.x;
    if (idx >= NE) return;
    int x = idx % W;
    int base = idx - x;
    float sa = 0.f, sb = 0.f;
#pragma unroll
    for (int d = -2; d <= 2; d++) {
        int xx = x + d;
        xx = xx < 0 ? 0 : (xx > W - 1 ? W - 1 : xx);
        sa += a[base + xx];
        sb += b[base + xx];
    }
    oa[idx] = sa;
    ob[idx] = sb;
}

// ---------------------------------------------------------------------------
// K4: stage-2 front: g = (im - boxsum/125)^2 computed on the fly, then x-pass.
__global__ void k_boxx_g_pair(const float* __restrict__ f, const float* __restrict__ m,
                              const float* __restrict__ s1f, const float* __restrict__ s1m,
                              float* __restrict__ oa, float* __restrict__ ob) {
    int idx = blockIdx.x * blockDim.x + threadIdx.x;
    if (idx >= NE) return;
    int x = idx % W;
    int base = idx - x;
    float sa = 0.f, sb = 0.f;
#pragma unroll
    for (int d = -2; d <= 2; d++) {
        int xx = x + d;
        xx = xx < 0 ? 0 : (xx > W - 1 ? W - 1 : xx);
        int j = base + xx;
        float df = f[j] - s1f[j] * INV_SZ;
        float dm = m[j] - s1m[j] * INV_SZ;
        sa += df * df;
        sb += dm * dm;
    }
    oa[idx] = sa;
    ob[idx] = sb;
}

// ---------------------------------------------------------------------------
// K7: stage-3 front: p = nF*nM computed on the fly, then x-pass (single field out).
__global__ void k_boxx_p(const float* __restrict__ f, const float* __restrict__ m,
                         const float* __restrict__ s1f, const float* __restrict__ s1m,
                         const float* __restrict__ s2f, const float* __restrict__ s2m,
                         float* __restrict__ o) {
    int idx = blockIdx.x * blockDim.x + threadIdx.x;
    if (idx >= NE) return;
    int x = idx % W;
    int base = idx - x;
    float s = 0.f;
#pragma unroll
    for (int d = -2; d <= 2; d++) {
        int xx = x + d;
        xx = xx < 0 ? 0 : (xx > W - 1 ? W - 1 : xx);
        int j = base + xx;
        float uf = s1f[j] * INV_SZ;
        float um = s1m[j] * INV_SZ;
        float vf = s2f[j] * INV_SZ;
        float vm = s2m[j] * INV_SZ;
        float prod = fmaxf(vf * vm, 1e-24f);
        float rs = frsqrt_approx(prod);
        s += (f[j] - uf) * (m[j] - um) * rs;
    }
    o[idx] = s;
}

// ---------------------------------------------------------------------------
// Sliding 5-tap clamped sum along an axis (y or z), two fields.
// Column: fixed (n, mid, x); element i at base + i*elemStride, i in [0,160).
// y-pass: midStride=PLANE (mid=z), elemStride=W
// z-pass: midStride=W     (mid=y), elemStride=PLANE
__global__ void k_slide_pair(const float* __restrict__ a, const float* __restrict__ b,
                             float* __restrict__ oa, float* __restrict__ ob,
                             int midStride, int elemStride) {
    int tid = blockIdx.x * blockDim.x + threadIdx.x;
    if (tid >= SLIDE_THREADS) return;
    int c = tid % NCOL;
    int chunk = tid / NCOL;
    int x = c % W;
    int mid = (c / W) % 160;
    int n = c / (160 * W);
    int base = n * VOL + mid * midStride + x;
    int y0 = chunk * CHUNK;

    float sa = 0.f, sb = 0.f;
#pragma unroll
    for (int d = -2; d <= 2; d++) {
        int yy = y0 + d;
        yy = yy < 0 ? 0 : (yy > 159 ? 159 : yy);
        sa += a[base + yy * elemStride];
        sb += b[base + yy * elemStride];
    }
#pragma unroll 4
    for (int j = 0; j < CHUNK; j++) {
        int y = y0 + j;
        oa[base + y * elemStride] = sa;
        ob[base + y * elemStride] = sb;
        int yn = y + 3 > 159 ? 159 : y + 3;
        int yo = y - 2 < 0 ? 0 : y - 2;
        sa += a[base + yn * elemStride] - a[base + yo * elemStride];
        sb += b[base + yn * elemStride] - b[base + yo * elemStride];
    }
}

// Single-field variant (stage-3 y-pass)
__global__ void k_slide_one(const float* __restrict__ a, float* __restrict__ oa,
                            int midStride, int elemStride) {
    int tid = blockIdx.x * blockDim.x + threadIdx.x;
    if (tid >= SLIDE_THREADS) return;
    int c = tid % NCOL;
    int chunk = tid / NCOL;
    int x = c % W;
    int mid = (c / W) % 160;
    int n = c / (160 * W);
    int base = n * VOL + mid * midStride + x;
    int y0 = chunk * CHUNK;

    float sa = 0.f;
#pragma unroll
    for (int d = -2; d <= 2; d++) {
        int yy = y0 + d;
        yy = yy < 0 ? 0 : (yy > 159 ? 159 : yy);
        sa += a[base + yy * elemStride];
    }
#pragma unroll 4
    for (int j = 0; j < CHUNK; j++) {
        int y = y0 + j;
        oa[base + y * elemStride] = sa;
        int yn = y + 3 > 159 ? 159 : y + 3;
        int yo = y - 2 < 0 ? 0 : y - 2;
        sa += a[base + yn * elemStride] - a[base + yo * elemStride];
    }
}

// ---------------------------------------------------------------------------
// K9: final z-pass (sliding) fused with masked -sum(cross^2) reduction.
// elemStride = PLANE, midStride = W.
__global__ void k_slide_reduce(const float* __restrict__ a, const float* __restrict__ mask) {
    __shared__ double sdata[256];
    int tid = blockIdx.x * blockDim.x + threadIdx.x;
    double acc = 0.0;
    if (tid < SLIDE_THREADS) {
        int c = tid % NCOL;
        int chunk = tid / NCOL;
        int x = c % W;
        int mid = (c / W) % 160;   // y
        int n = c / (160 * W);
        int base = n * VOL + mid * W + x;
        int y0 = chunk * CHUNK;

        float sa = 0.f;
#pragma unroll
        for (int d = -2; d <= 2; d++) {
            int yy = y0 + d;
            yy = yy < 0 ? 0 : (yy > 159 ? 159 : yy);
            sa += a[base + yy * PLANE];
        }
#pragma unroll 4
        for (int j = 0; j < CHUNK; j++) {
            int y = y0 + j;
            float cross = sa;
            acc += (double)(cross * cross * mask[base + y * PLANE]);
            int yn = y + 3 > 159 ? 159 : y + 3;
            int yo = y - 2 < 0 ? 0 : y - 2;
            sa += a[base + yn * PLANE] - a[base + yo * PLANE];
        }
    }
    int t = threadIdx.x;
    sdata[t] = acc;
    __syncthreads();
    for (int s = 128; s > 0; s >>= 1) {
        if (t < s) sdata[t] += sdata[t + s];
        __syncthreads();
    }
    if (t == 0) atomicAdd(&g_acc, sdata[0]);
}

// K10: finalize
__global__ void k_finish(float* __restrict__ out) {
    out[0] = (float)(-g_acc);
}

// ---------------------------------------------------------------------------
extern "C" void kernel_launch(void* const* d_in, const int* in_sizes, int n_in,
                              void* d_out, int out_size) {
    const float* f    = (const float*)d_in[0];
    const float* m    = (const float*)d_in[1];
    const float* mask = (const float*)d_in[2];
    float* out = (float*)d_out;

    float* s1f = nullptr; cudaGetSymbolAddress((void**)&s1f, g_s1f);
    float* s1m = nullptr; cudaGetSymbolAddress((void**)&s1m, g_s1m);
    float* s2f = nullptr; cudaGetSymbolAddress((void**)&s2f, g_s2f);
    float* s2m = nullptr; cudaGetSymbolAddress((void**)&s2m, g_s2m);
    float* t0  = nullptr; cudaGetSymbolAddress((void**)&t0, g_t0);
    float* t1  = nullptr; cudaGetSymbolAddress((void**)&t1, g_t1);
    float* t2  = nullptr; cudaGetSymbolAddress((void**)&t2, g_t2);
    float* t3  = nullptr; cudaGetSymbolAddress((void**)&t3, g_t3);

    const int TB = 256;
    const int gridE = (NE + TB - 1) / TB;            // 32000
    const int gridS = (SLIDE_THREADS + TB - 1) / TB; // 1000

    k_zero_acc<<<1, 1>>>();

    // Stage 1: box(F), box(M)
    k_boxx_pair<<<gridE, TB>>>(f, m, t0, t1);
    k_slide_pair<<<gridS, TB>>>(t0, t1, t2, t3, PLANE, W);   // y
    k_slide_pair<<<gridS, TB>>>(t2, t3, s1f, s1m, W, PLANE); // z

    // Stage 2: box((im - u)^2)
    k_boxx_g_pair<<<gridE, TB>>>(f, m, s1f, s1m, t0, t1);
    k_slide_pair<<<gridS, TB>>>(t0, t1, t2, t3, PLANE, W);   // y
    k_slide_pair<<<gridS, TB>>>(t2, t3, s2f, s2m, W, PLANE); // z

    // Stage 3: box(nF * nM), then -sum(cross^2 * mask)
    k_boxx_p<<<gridE, TB>>>(f, m, s1f, s1m, s2f, s2m, t0);
    k_slide_one<<<gridS, TB>>>(t0, t1, PLANE, W);            // y
    k_slide_reduce<<<gridS, TB>>>(t1, mask);                 // z + reduce

    k_finish<<<1, 1>>>(out);
    (void)in_sizes; (void)n_in; (void)out_size;
}